// round 16
// baseline (speedup 1.0000x reference)
#include <cuda_runtime.h>
#include <math.h>

// Problem constants
#define NN     32
#define CC     512
#define HH     56
#define WW     56
#define HW     (HH * WW)          // 3136 floats per (n,c) row
#define FF     8                  // frequencies
#define OO     32                 // C / R
#define ROWS   (NN * CC)          // 16384
#define J_ROW  (HW / 4)           // 784 float4 per row

// L2-pipelined grouping: 8 samples per group (51 MB of x -> L2-resident)
#define GN       8                         // samples per group
#define NGROUPS  (NN / GN)                 // 4
#define G_ROWS   (GN * CC)                 // 4096 rows per group
#define G_F4     (G_ROWS * J_ROW)          // 3,211,264 float4 per group

// sqrt(1/56) and sqrt(2/56)
#define B0S 0.1336306209562122f
#define BGS 0.1889822365046136f

// Scratch (no cudaMalloc allowed): intermediates live in device globals.
__device__ float g_y[NN * FF * CC];   // pooled DCT features (n, f, c)
__device__ float g_s[NN * CC];        // per-(n,c) sigmoid scale

__device__ __forceinline__ float dot4(float4 a, float4 b) {
    return fmaf(a.x, b.x, fmaf(a.y, b.y, fmaf(a.z, b.z, a.w * b.w)));
}

// f -> (gH, gW): [ (0,0) (0,1) (1,0) (1,1) (0,3) (3,0) (0,2) (2,0) ]
__device__ __forceinline__ void accum(float acc[FF], float4 c, float4 bh,
                                      float4 w0, float4 w1,
                                      float4 w2, float4 w3)
{
    const float d0 = dot4(c, w0), d1 = dot4(c, w1);
    const float d2 = dot4(c, w2), d3 = dot4(c, w3);
    acc[0] = fmaf(bh.x, d0, acc[0]);
    acc[1] = fmaf(bh.x, d1, acc[1]);
    acc[2] = fmaf(bh.y, d0, acc[2]);
    acc[3] = fmaf(bh.y, d1, acc[3]);
    acc[4] = fmaf(bh.x, d3, acc[4]);
    acc[5] = fmaf(bh.w, d0, acc[5]);
    acc[6] = fmaf(bh.x, d2, acc[6]);
    acc[7] = fmaf(bh.z, d0, acc[7]);
}

// ---------------------------------------------------------------------------
// Kernel 1: multi-frequency DCT pooling, separable, fixed-wq lanes.
// v7: ONE channel row per warp (group grids are 1024 blocks -> 6.9 CTAs/SM,
// same chip-wide loads-in-flight as v6 at full-batch size). Lane l<28 owns
// W-column block wq=l%14 and row parity dh=l/14; 4 bW float4s are
// loop-invariant registers. Per iteration: 2 batched LDG.128, 2 LDS, 48 FMA.
// Grid (per group): G_ROWS/4 = 1024 blocks x 128 thr.
// ---------------------------------------------------------------------------
__global__ __launch_bounds__(128, 7)
void freq_pool_kernel(const float* __restrict__ x, int row_base)
{
    __shared__ float4 sBH[56];      // sBH[h] = {b0,b1,b2,b3}(h)
    __shared__ float4 sBW[4][14];   // sBW[g][wq] = b_g(4wq .. 4wq+3)

    const int tid = threadIdx.x;
    if (tid < 56) {
        const float p = (tid + 0.5f) / 56.0f;
        sBH[tid] = make_float4(B0S,
                               cospif(1.0f * p) * BGS,
                               cospif(2.0f * p) * BGS,
                               cospif(3.0f * p) * BGS);
    } else if (tid >= 64 && tid < 120) {
        const int idx = tid - 64;
        const int g = idx / 14, wq = idx - g * 14;
        const float s = g ? BGS : B0S;
        const float fg = (float)g;
        float4 v;
        v.x = cospif(fg * (4 * wq + 0.5f) / 56.0f) * s;
        v.y = cospif(fg * (4 * wq + 1.5f) / 56.0f) * s;
        v.z = cospif(fg * (4 * wq + 2.5f) / 56.0f) * s;
        v.w = cospif(fg * (4 * wq + 3.5f) / 56.0f) * s;
        sBW[g][wq] = v;
    }
    __syncthreads();

    const int warp = tid >> 5;
    const int lane = tid & 31;
    const int row  = row_base + blockIdx.x * 4 + warp;   // one channel row

    const bool active = lane < 28;
    const int  wq = active ? (lane % 14) : 0;
    const int  dh = active ? (lane / 14) : 0;

    float4 bw0 = sBW[0][wq];
    float4 bw1 = sBW[1][wq];
    float4 bw2 = sBW[2][wq];
    float4 bw3 = sBW[3][wq];
    if (!active) {
        bw0 = make_float4(0.f, 0.f, 0.f, 0.f);
        bw1 = bw0; bw2 = bw0; bw3 = bw0;
    }

    const float4* xb = (const float4*)x + (size_t)row * J_ROW;

    float acc[FF];
#pragma unroll
    for (int f = 0; f < FF; f++) acc[f] = 0.0f;

    // 14 iterations x 2 image rows each (h = 4it + dh and +2, dh covers rest).
#pragma unroll 2
    for (int it = 0; it < 14; it++) {
        const int hA = 4 * it + dh;
        const int hB = hA + 2;
        const int pA = hA * 14 + wq;
        const int pB = hB * 14 + wq;

        const float4 cA = xb[pA];           // 2 independent LDG.128
        const float4 cB = xb[pB];

        const float4 bhA = sBH[hA];
        const float4 bhB = sBH[hB];

        accum(acc, cA, bhA, bw0, bw1, bw2, bw3);
        accum(acc, cB, bhB, bw0, bw1, bw2, bw3);
    }

    // Warp reduce; lane 0 stores.
    const int n = row >> 9;             // /CC
    const int c = row & (CC - 1);
#pragma unroll
    for (int f = 0; f < FF; f++) {
        float v = acc[f];
#pragma unroll
        for (int off = 16; off > 0; off >>= 1)
            v += __shfl_xor_sync(0xffffffffu, v, off);
        if (lane == 0)
            g_y[(size_t)n * FF * CC + f * CC + c] = v;
    }
}

// ---------------------------------------------------------------------------
// Kernel 2: squeeze-excite MLP (tiny). One block per sample n (per group).
//   z[f,o] = relu( sum_c y[n,f,c] * w1[f,o,c] )        (w1: (8,32,512))
//   s[c]   = sigmoid( sum_{f,o} z[f,o] * w2[c,f,o] )   (w2: (512,8,32))
// ---------------------------------------------------------------------------
__global__ __launch_bounds__(256, 4)
void freq_mlp_kernel(const float* __restrict__ w1,
                     const float* __restrict__ w2, int n_base)
{
    __shared__ __align__(16) float zs[FF * OO];   // 256 floats

    const int n = n_base + blockIdx.x;
    const int t = threadIdx.x;

    // Phase A: 256 threads -> one (f,o) each, dot over C=512.
    {
        const int f = t >> 5;
        const int o = t & 31;
        const float4* yv = (const float4*)(g_y + (size_t)n * FF * CC + f * CC);
        const float4* wv = (const float4*)(w1 + (size_t)(f * OO + o) * CC);
        float s = 0.0f;
#pragma unroll 8
        for (int i = 0; i < CC / 4; i++) {
            float4 a = yv[i];
            float4 b = wv[i];
            s = fmaf(a.x, b.x, fmaf(a.y, b.y, fmaf(a.z, b.z, fmaf(a.w, b.w, s))));
        }
        zs[f * OO + o] = fmaxf(s, 0.0f);
    }
    __syncthreads();

    // Phase B: each thread handles 2 output channels, dot over F*O=256.
    for (int c = t; c < CC; c += 256) {
        const float4* wv = (const float4*)(w2 + (size_t)c * FF * OO);
        const float4* zv = (const float4*)zs;
        float s = 0.0f;
#pragma unroll 8
        for (int i = 0; i < (FF * OO) / 4; i++) {
            float4 a = zv[i];
            float4 b = wv[i];
            s = fmaf(a.x, b.x, fmaf(a.y, b.y, fmaf(a.z, b.z, fmaf(a.w, b.w, s))));
        }
        g_s[n * CC + c] = 1.0f / (1.0f + __expf(-s));
    }
}

// ---------------------------------------------------------------------------
// Kernel 3: broadcast channel scale.
// Grouped: reads should hit L2 (x chunk just streamed by this group's pool).
// Plain (cached) loads; __stcs evict-first stores so writes don't evict x.
// Grid (per group): G_F4/1024 = 3136 blocks x 256 thr, 4 float4/thread.
// ---------------------------------------------------------------------------
__global__ __launch_bounds__(256, 8)
void freq_scale_kernel(const float* __restrict__ x,
                       float* __restrict__ out, int f4_base)
{
    const int base = f4_base + blockIdx.x * 1024 + threadIdx.x;
    const int i0 = base;
    const int i1 = base + 256;
    const int i2 = base + 512;
    const int i3 = base + 768;

    float4 v0 = ((const float4*)x)[i0];
    float4 v1 = ((const float4*)x)[i1];
    float4 v2 = ((const float4*)x)[i2];
    float4 v3 = ((const float4*)x)[i3];

    const float s0 = __ldg(&g_s[i0 / J_ROW]);
    const float s1 = __ldg(&g_s[i1 / J_ROW]);
    const float s2 = __ldg(&g_s[i2 / J_ROW]);
    const float s3 = __ldg(&g_s[i3 / J_ROW]);

    v0.x *= s0; v0.y *= s0; v0.z *= s0; v0.w *= s0;
    v1.x *= s1; v1.y *= s1; v1.z *= s1; v1.w *= s1;
    v2.x *= s2; v2.y *= s2; v2.z *= s2; v2.w *= s2;
    v3.x *= s3; v3.y *= s3; v3.z *= s3; v3.w *= s3;

    __stcs((float4*)out + i0, v0);
    __stcs((float4*)out + i1, v1);
    __stcs((float4*)out + i2, v2);
    __stcs((float4*)out + i3, v3);
}

// ---------------------------------------------------------------------------
// Launch. Inputs (metadata order): x, dct, w1, w2. Output: fp32 (N,C,H,W).
// 4 groups of 8 samples: pool(g) -> mlp(g) -> scale(g). scale(g) rereads the
// 51 MB x-chunk that pool(g) just pulled into L2.
// ---------------------------------------------------------------------------
extern "C" void kernel_launch(void* const* d_in, const int* in_sizes, int n_in,
                              void* d_out, int out_size)
{
    const float* x   = (const float*)d_in[0];
    const float* w1  = (const float*)d_in[2];
    const float* w2  = (const float*)d_in[3];
    float* out = (float*)d_out;

    for (int g = 0; g < NGROUPS; g++) {
        freq_pool_kernel<<<G_ROWS / 4, 128>>>(x, g * G_ROWS);
        freq_mlp_kernel<<<GN, 256>>>(w1, w2, g * GN);
        freq_scale_kernel<<<G_F4 / 1024, 256>>>(x, out, g * G_F4);
    }
}

// round 17
// speedup vs baseline: 1.3183x; 1.3183x over previous
#include <cuda_runtime.h>
#include <math.h>

// Problem constants
#define NN     32
#define CC     512
#define HH     56
#define WW     56
#define HW     (HH * WW)          // 3136 floats per (n,c) row
#define FF     8
#define OO     32                 // C / R
#define ROWS   (NN * CC)          // 16384
#define J_ROW  (HW / 4)           // 784 float4 per row

// Work queue: 8 channel-rows per item
#define POOL_ITEMS   2048
#define SCALE_ITEMS  2048
#define TOTAL_ITEMS  (POOL_ITEMS + SCALE_ITEMS)
#define ITEMS_PER_N  64           // pool items per sample (512 rows / 8)

// sqrt(1/56) and sqrt(2/56)
#define B0S 0.1336306209562122f
#define BGS 0.1889822365046136f

// Scratch + sync state (no cudaMalloc allowed)
__device__ float g_y[NN * FF * CC];
__device__ float g_s[NN * CC];
__device__ int   g_ticket;
__device__ int   g_done[NN];
__device__ int   g_flag[NN];

__device__ __forceinline__ float dot4(float4 a, float4 b) {
    return fmaf(a.x, b.x, fmaf(a.y, b.y, fmaf(a.z, b.z, a.w * b.w)));
}

// f -> (gH, gW): [ (0,0) (0,1) (1,0) (1,1) (0,3) (3,0) (0,2) (2,0) ]
__device__ __forceinline__ void accum(float acc[FF], float4 c, float4 bh,
                                      float4 w0, float4 w1,
                                      float4 w2, float4 w3)
{
    const float d0 = dot4(c, w0), d1 = dot4(c, w1);
    const float d2 = dot4(c, w2), d3 = dot4(c, w3);
    acc[0] = fmaf(bh.x, d0, acc[0]);
    acc[1] = fmaf(bh.x, d1, acc[1]);
    acc[2] = fmaf(bh.y, d0, acc[2]);
    acc[3] = fmaf(bh.y, d1, acc[3]);
    acc[4] = fmaf(bh.x, d3, acc[4]);
    acc[5] = fmaf(bh.w, d0, acc[5]);
    acc[6] = fmaf(bh.x, d2, acc[6]);
    acc[7] = fmaf(bh.z, d0, acc[7]);
}

// ---------------------------------------------------------------------------
// Init: reset queue state every launch (graph-replay safe, deterministic).
// ---------------------------------------------------------------------------
__global__ void fca_init_kernel()
{
    const int t = threadIdx.x;
    if (t == 0) g_ticket = 0;
    if (t < NN) { g_done[t] = 0; g_flag[t] = 0; }
}

// ---------------------------------------------------------------------------
// Fused persistent kernel: dynamic ticket queue.
//   tickets [0, 2048)    : pool item  = 8 channel rows (DCT pooling, v6 math)
//   tickets [2048, 4096) : scale item = 8 channel rows (gated on flag[n])
// Last pool-finisher per sample runs the SE-MLP inline and raises flag[n].
// Pool reads of late samples overlap scale read+write of early samples.
// ---------------------------------------------------------------------------
__global__ __launch_bounds__(128, 7)
void fca_fused_kernel(const float* __restrict__ x,
                      const float* __restrict__ w1,
                      const float* __restrict__ w2,
                      float* __restrict__ out)
{
    __shared__ float4 sBH[56];      // H basis {b0,b1,b2,b3}(h)
    __shared__ float4 sBW[4][14];   // W basis b_g(4wq..4wq+3)
    __shared__ __align__(16) float zs[FF * OO];
    __shared__ float ss[8];
    __shared__ int   s_wid;
    __shared__ int   s_last;

    const int tid = threadIdx.x;

    // Build separable DCT bases (1.8 KB) once per block.
    if (tid < 56) {
        const float p = (tid + 0.5f) / 56.0f;
        sBH[tid] = make_float4(B0S,
                               cospif(1.0f * p) * BGS,
                               cospif(2.0f * p) * BGS,
                               cospif(3.0f * p) * BGS);
    } else if (tid >= 64 && tid < 120) {
        const int idx = tid - 64;
        const int g = idx / 14, wq = idx - g * 14;
        const float s = g ? BGS : B0S;
        const float fg = (float)g;
        float4 v;
        v.x = cospif(fg * (4 * wq + 0.5f) / 56.0f) * s;
        v.y = cospif(fg * (4 * wq + 1.5f) / 56.0f) * s;
        v.z = cospif(fg * (4 * wq + 2.5f) / 56.0f) * s;
        v.w = cospif(fg * (4 * wq + 3.5f) / 56.0f) * s;
        sBW[g][wq] = v;
    }
    __syncthreads();

    const int warp = tid >> 5;
    const int lane = tid & 31;
    const bool active = lane < 28;
    const int  wq = active ? (lane % 14) : 0;
    const int  dh = active ? (lane / 14) : 0;

    float4 bw0 = sBW[0][wq];
    float4 bw1 = sBW[1][wq];
    float4 bw2 = sBW[2][wq];
    float4 bw3 = sBW[3][wq];
    if (!active) {
        bw0 = make_float4(0.f, 0.f, 0.f, 0.f);
        bw1 = bw0; bw2 = bw0; bw3 = bw0;
    }

    while (true) {
        if (tid == 0) s_wid = atomicAdd(&g_ticket, 1);
        __syncthreads();
        const int wid = s_wid;
        __syncthreads();                    // s_wid reusable next iteration
        if (wid >= TOTAL_ITEMS) break;

        if (wid < POOL_ITEMS) {
            // ---------------- POOL item: 8 rows, 2 per warp ----------------
            const int row0 = wid * 8 + warp * 2;
            const float4* xb = (const float4*)x + (size_t)row0 * J_ROW;

            float acc0[FF], acc1[FF];
#pragma unroll
            for (int f = 0; f < FF; f++) { acc0[f] = 0.0f; acc1[f] = 0.0f; }

#pragma unroll 2
            for (int it = 0; it < 14; it++) {
                const int hA = 4 * it + dh;
                const int hB = hA + 2;
                const int pA = hA * 14 + wq;
                const int pB = hB * 14 + wq;

                const float4 cA0 = xb[pA];
                const float4 cA1 = xb[pA + J_ROW];
                const float4 cB0 = xb[pB];
                const float4 cB1 = xb[pB + J_ROW];

                const float4 bhA = sBH[hA];
                const float4 bhB = sBH[hB];

                accum(acc0, cA0, bhA, bw0, bw1, bw2, bw3);
                accum(acc1, cA1, bhA, bw0, bw1, bw2, bw3);
                accum(acc0, cB0, bhB, bw0, bw1, bw2, bw3);
                accum(acc1, cB1, bhB, bw0, bw1, bw2, bw3);
            }

            const int n = row0 >> 9;
#pragma unroll
            for (int r = 0; r < 2; r++) {
                const int row = row0 + r;
                const int c = row & (CC - 1);
#pragma unroll
                for (int f = 0; f < FF; f++) {
                    float v = r ? acc1[f] : acc0[f];
#pragma unroll
                    for (int off = 16; off > 0; off >>= 1)
                        v += __shfl_xor_sync(0xffffffffu, v, off);
                    if (lane == 0)
                        g_y[(size_t)n * FF * CC + f * CC + c] = v;
                }
            }

            __threadfence();                // y visible device-wide
            __syncthreads();
            if (tid == 0) {
                const int c = atomicAdd(&g_done[n], 1);
                s_last = (c == ITEMS_PER_N - 1);
            }
            __syncthreads();

            if (s_last) {
                // ---- inline SE-MLP for sample n (128 threads) ----
                // Phase A: 256 (f,o) pairs, 2 per thread; dot over C=512.
                for (int p = tid; p < FF * OO; p += 128) {
                    const int f = p >> 5;
                    const int o = p & 31;
                    const float4* yv = (const float4*)(g_y + (size_t)n * FF * CC + f * CC);
                    const float4* wv = (const float4*)(w1 + (size_t)(f * OO + o) * CC);
                    float s = 0.0f;
#pragma unroll 8
                    for (int i = 0; i < CC / 4; i++) {
                        float4 a = yv[i];
                        float4 b = wv[i];
                        s = fmaf(a.x, b.x, fmaf(a.y, b.y, fmaf(a.z, b.z, fmaf(a.w, b.w, s))));
                    }
                    zs[p] = fmaxf(s, 0.0f);
                }
                __syncthreads();
                // Phase B: 512 channels, 4 per thread; dot over F*O=256.
                for (int c = tid; c < CC; c += 128) {
                    const float4* wv = (const float4*)(w2 + (size_t)c * FF * OO);
                    const float4* zv = (const float4*)zs;
                    float s = 0.0f;
#pragma unroll 8
                    for (int i = 0; i < (FF * OO) / 4; i++) {
                        float4 a = zv[i];
                        float4 b = wv[i];
                        s = fmaf(a.x, b.x, fmaf(a.y, b.y, fmaf(a.z, b.z, fmaf(a.w, b.w, s))));
                    }
                    g_s[n * CC + c] = 1.0f / (1.0f + __expf(-s));
                }
                __threadfence();            // s visible device-wide
                __syncthreads();
                if (tid == 0) atomicExch(&g_flag[n], 1);
                __syncthreads();            // zs reusable next iteration
            }
        } else {
            // ---------------- SCALE item: 8 rows ----------------
            const int sit  = wid - POOL_ITEMS;
            const int row0 = sit * 8;
            const int n    = row0 >> 9;

            if (tid == 0) {
                while (atomicAdd(&g_flag[n], 0) == 0) __nanosleep(128);
            }
            __syncthreads();
            if (tid < 8) ss[tid] = g_s[row0 + tid];
            __syncthreads();

            const float4* xi = (const float4*)x   + (size_t)row0 * J_ROW;
            float4*       oo = (float4*)out       + (size_t)row0 * J_ROW;

            // 8 rows = 6272 float4; 128 thr: 12 batches of 4 + 1 tail each.
#pragma unroll 1
            for (int k = 0; k < 48; k += 4) {
                const int i0 = tid + 128 * k;
                const int i1 = i0 + 128;
                const int i2 = i0 + 256;
                const int i3 = i0 + 384;
                float4 v0 = xi[i0];
                float4 v1 = xi[i1];
                float4 v2 = xi[i2];
                float4 v3 = xi[i3];
                const float s0 = ss[i0 / J_ROW];
                const float s1 = ss[i1 / J_ROW];
                const float s2 = ss[i2 / J_ROW];
                const float s3 = ss[i3 / J_ROW];
                v0.x *= s0; v0.y *= s0; v0.z *= s0; v0.w *= s0;
                v1.x *= s1; v1.y *= s1; v1.z *= s1; v1.w *= s1;
                v2.x *= s2; v2.y *= s2; v2.z *= s2; v2.w *= s2;
                v3.x *= s3; v3.y *= s3; v3.z *= s3; v3.w *= s3;
                __stcs(oo + i0, v0);
                __stcs(oo + i1, v1);
                __stcs(oo + i2, v2);
                __stcs(oo + i3, v3);
            }
            {
                const int i = tid + 6144;   // 6144..6271: all threads valid
                float4 v = xi[i];
                const float s = ss[i / J_ROW];
                v.x *= s; v.y *= s; v.z *= s; v.w *= s;
                __stcs(oo + i, v);
            }
            __syncthreads();                // ss reusable next iteration
        }
    }
}

// ---------------------------------------------------------------------------
// Launch. Inputs (metadata order): x, dct, w1, w2. Output: fp32 (N,C,H,W).
// ---------------------------------------------------------------------------
extern "C" void kernel_launch(void* const* d_in, const int* in_sizes, int n_in,
                              void* d_out, int out_size)
{
    const float* x   = (const float*)d_in[0];
    const float* w1  = (const float*)d_in[2];
    const float* w2  = (const float*)d_in[3];
    float* out = (float*)d_out;

    fca_init_kernel<<<1, 64>>>();
    fca_fused_kernel<<<1036, 128>>>(x, w1, w2, out);
}